// round 15
// baseline (speedup 1.0000x reference)
#include <cuda_runtime.h>
#include <cuda_fp16.h>
#include <stdint.h>

#define N_MAX 50000
#define E_MAX 600000
#define CSR_BLOCKS 98
#define CSR_THREADS 512
#define CSR_TOTAL (CSR_BLOCKS * CSR_THREADS)   // 50176 threads
#define EPT 6                                   // edge PAIRS per thread (6*50176*2 >= 600k)

// Scratch (device globals; no allocation allowed)
__device__ int      g_cnt[N_MAX];            // zero at entry (re-zeroed in scan phase)
__device__ int      g_off[N_MAX + 1];
__device__ int      g_bsum[CSR_BLOCKS];
__device__ int      g_flag[CSR_BLOCKS + 1];  // cleared in phase 1 each run
__device__ unsigned g_barrier[2];            // generation counters, never reset
__device__ float    g_dinv[N_MAX];
__device__ int      g_csr[E_MAX];
__device__ __half   g_h[(size_t)N_MAX * 128];   // x @ W1 (fp16)
__device__ __half   g_agg[(size_t)N_MAX * 128]; // aggregated layer-1 (fp16)
__device__ __half   g_t[(size_t)N_MAX * 64];    // relu_h @ W2 (fp16)

__device__ __forceinline__ float tf32r(float x) {
    uint32_t u;
    asm("cvt.rna.tf32.f32 %0, %1;" : "=r"(u) : "f"(x));
    return __uint_as_float(u);
}

__device__ __forceinline__ void mma_tf32(float* c, const uint32_t* a, const uint32_t* b) {
    asm volatile(
        "mma.sync.aligned.m16n8k8.row.col.f32.tf32.tf32.f32 "
        "{%0,%1,%2,%3}, {%4,%5,%6,%7}, {%8,%9}, {%0,%1,%2,%3};"
        : "+f"(c[0]), "+f"(c[1]), "+f"(c[2]), "+f"(c[3])
        : "r"(a[0]), "r"(a[1]), "r"(a[2]), "r"(a[3]), "r"(b[0]), "r"(b[1]));
}

// In-block dtype detection: sample 32 odd int32 words. int64 data (values <
// 2^31) has zero hi-words there; int32 random node ids are ~never all zero.
__device__ __forceinline__ int detect_fmt(const int* __restrict__ raw, int E) {
    int idx = 2 * (threadIdx.x & 31) + 1;
    int hw = (idx < 2 * E) ? raw[idx] : 0;
    unsigned any = __ballot_sync(0xFFFFFFFFu, hw != 0);
    return (any == 0) ? 1 : 0;   // 1 = int64, 0 = int32
}

// Generation-based grid barrier: each replay adds exactly CSR_BLOCKS arrivals,
// so target = (ticket/CSR_BLOCKS + 1)*CSR_BLOCKS needs no counter reset.
__device__ __forceinline__ void grid_bar(int idx) {
    __threadfence();
    __syncthreads();
    __shared__ unsigned tgt;
    if (threadIdx.x == 0) {
        unsigned t = atomicAdd(&g_barrier[idx], 1u);
        tgt = (t / CSR_BLOCKS + 1u) * CSR_BLOCKS;
    }
    __syncthreads();
    if (threadIdx.x == 0) {
        while (*(volatile unsigned*)&g_barrier[idx] < tgt) {}
    }
    __syncthreads();
    __threadfence();
}

// Load 2 adjacent edge values. base even; vector paths require E even.
__device__ __forceinline__ void load_pair(const int* __restrict__ raw, int off64,
                                          int off32, int fmt, bool two, bool vec,
                                          int& v0, int& v1) {
    if (fmt) {
        if (two && vec) { int4 v = *(const int4*)&raw[off64]; v0 = v.x; v1 = v.z; }
        else { v0 = raw[off64]; v1 = two ? raw[off64 + 2] : 0; }
    } else {
        if (two && vec) { int2 v = *(const int2*)&raw[off32]; v0 = v.x; v1 = v.y; }
        else { v0 = raw[off32]; v1 = two ? raw[off32 + 1] : 0; }
    }
}

// ---------------------------------------------------------------------------
// Fused CSR build: count(+rank, in-register) -> bar -> scan(+dinv) -> bar -> fill
// ---------------------------------------------------------------------------
__global__ void __launch_bounds__(CSR_THREADS) k_csr(const int* __restrict__ raw,
                                                     int E, int n) {
    __shared__ int s_fmt;
    __shared__ int warpsum[16];
    __shared__ int pred[4];

    const int t   = threadIdx.x;
    const int b   = blockIdx.x;
    const int gid = b * CSR_THREADS + t;
    const bool vec = ((E & 1) == 0);

    if (t < 32) {
        int f = detect_fmt(raw, E);
        if (t == 0) s_fmt = f;
    }
    if (gid <= CSR_BLOCKS) g_flag[gid] = 0;   // clear lookback flags (block 0)
    __syncthreads();
    const int fmt = s_fmt;

    // ---- phase 1: count + hold (src|dst<<16, rank) in registers ----
    unsigned sd[2 * EPT];
    int      rk[2 * EPT];
#pragma unroll
    for (int k = 0; k < EPT; k++) {
        int base = 2 * (gid + k * CSR_TOTAL);
        if (base < E) {
            bool two = (base + 1 < E);
            int s0, s1, d0, d1;
            load_pair(raw, 2 * base,       base,     fmt, two, vec, s0, s1);
            load_pair(raw, 2 * (E + base), E + base, fmt, two, vec, d0, d1);
            s0 = min(max(s0, 0), n - 1); d0 = min(max(d0, 0), n - 1);
            sd[2 * k] = (unsigned)s0 | ((unsigned)d0 << 16);
            rk[2 * k] = atomicAdd(&g_cnt[d0], 1);
            if (two) {
                s1 = min(max(s1, 0), n - 1); d1 = min(max(d1, 0), n - 1);
                sd[2 * k + 1] = (unsigned)s1 | ((unsigned)d1 << 16);
                rk[2 * k + 1] = atomicAdd(&g_cnt[d1], 1);
            }
        }
    }

    grid_bar(0);

    // ---- phase 2: scan (decoupled lookback) + dinv + cnt re-zero ----
    {
        const int i = b * CSR_THREADS + t;
        const int v = (i < n) ? g_cnt[i] : 0;
        const int lane = t & 31, w = t >> 5;

        int x = v;
#pragma unroll
        for (int d = 1; d < 32; d <<= 1) {
            int y = __shfl_up_sync(0xFFFFFFFFu, x, d);
            if (lane >= d) x += y;
        }
        if (lane == 31) warpsum[w] = x;
        __syncthreads();
        if (w == 0) {
            int s = (lane < 16) ? warpsum[lane] : 0;
#pragma unroll
            for (int d = 1; d < 32; d <<= 1) {
                int y = __shfl_up_sync(0xFFFFFFFFu, s, d);
                if (lane >= d) s += y;
            }
            if (lane < 16) warpsum[lane] = s;
        }
        __syncthreads();
        const int base  = (w > 0) ? warpsum[w - 1] : 0;
        const int total = warpsum[15];

        if (t == 0) {
            g_bsum[b] = total;
            __threadfence();
            ((volatile int*)g_flag)[b] = 1;
        }

        int pv = 0;
        if (t < b) {                         // b <= 97 < 128
            while (((volatile int*)g_flag)[t] == 0) {}
            __threadfence();
            pv = g_bsum[t];
        }
        if (t < 128) {
            int s = pv;
#pragma unroll
            for (int d = 16; d > 0; d >>= 1) s += __shfl_down_sync(0xFFFFFFFFu, s, d);
            if ((t & 31) == 0) pred[t >> 5] = s;
        }
        __syncthreads();
        const int prefix = pred[0] + pred[1] + pred[2] + pred[3];

        if (i < n) {
            g_off[i] = prefix + base + x - v;        // global exclusive
            g_dinv[i] = rsqrtf((float)v + 1.0f);     // +1 self loop
            g_cnt[i] = 0;                            // re-zero for next replay
        }
        if (b == 0 && t == 0) g_off[n] = E;
    }

    grid_bar(1);

    // ---- phase 3: fill from registers (atomic-free, raw-free) ----
#pragma unroll
    for (int k = 0; k < EPT; k++) {
        int base = 2 * (gid + k * CSR_TOTAL);
        if (base < E) {
            unsigned p0 = sd[2 * k];
            g_csr[g_off[p0 >> 16] + rk[2 * k]] = (int)(p0 & 0xffffu);
            if (base + 1 < E) {
                unsigned p1 = sd[2 * k + 1];
                g_csr[g_off[p1 >> 16] + rk[2 * k + 1]] = (int)(p1 & 0xffffu);
            }
        }
    }
}

// ---------------------------------------------------------------------------
// tf32 tensor-core GEMM: H[n, OUTC] = X[n,128] @ W[128, OUTC]
// InT/OutT = float or __half. CTA tile 256x64, 8 warps, K sliced by 16.
// ---------------------------------------------------------------------------
template <int OUTC, typename InT, typename OutT>
__global__ void __launch_bounds__(256) k_gemm_mma(const InT* __restrict__ X,
                                                  const float* __restrict__ W,
                                                  OutT* __restrict__ H, int n) {
    __shared__ float As[32 * 33 * 4];
    __shared__ float Bs[16 * 33 * 2];
    const int tid   = threadIdx.x;
    const int lane  = tid & 31;
    const int warp  = tid >> 5;
    const int warpM = warp & 3;
    const int warpN = warp >> 2;
    const int row0  = blockIdx.x * 256;
    const int co    = blockIdx.y * 64;

    float c[4][4][4];
#pragma unroll
    for (int i = 0; i < 4; i++)
#pragma unroll
        for (int j = 0; j < 4; j++)
#pragma unroll
            for (int r = 0; r < 4; r++) c[i][j][r] = 0.f;

    for (int k0 = 0; k0 < 128; k0 += 16) {
#pragma unroll
        for (int f = tid; f < 1024; f += 256) {
            int r  = f >> 2;
            int kq = f & 3;
            int gr = min(row0 + r, n - 1);
            float4 v;
            if constexpr (sizeof(InT) == 2) {
                uint2 hv = *(const uint2*)&X[(size_t)gr * 128 + k0 + kq * 4];
                float2 f0 = __half22float2(*(__half2*)&hv.x);
                float2 f1 = __half22float2(*(__half2*)&hv.y);
                v = make_float4(f0.x, f0.y, f1.x, f1.y);
            } else {
                v = *(const float4*)&X[(size_t)gr * 128 + k0 + kq * 4];
            }
            int grp  = (r >> 4) * 2 + (kq >> 1);
            int lb   = (r & 7) * 4;
            int reg  = (kq & 1) * 2 + ((r >> 3) & 1);
            int sbase = grp * 33 * 4;
            As[(sbase + (lb + 0) * 4) + reg] = tf32r(v.x);
            As[(sbase + (lb + 1) * 4) + reg] = tf32r(v.y);
            As[(sbase + (lb + 2) * 4) + reg] = tf32r(v.z);
            As[(sbase + (lb + 3) * 4) + reg] = tf32r(v.w);
        }
        {
            int k  = tid >> 4;
            int nq = tid & 15;
            float4 v = *(const float4*)&W[(size_t)(k0 + k) * OUTC + co + nq * 4];
            int kstep = k >> 3, tg = k & 3, regb = (k >> 2) & 1;
            float vv[4] = {v.x, v.y, v.z, v.w};
#pragma unroll
            for (int j = 0; j < 4; j++) {
                int nn = nq * 4 + j;
                int grp = (nn >> 3) * 2 + kstep;
                Bs[(grp * 33 + (nn & 7) * 4 + tg) * 2 + regb] = tf32r(vv[j]);
            }
        }
        __syncthreads();

#pragma unroll
        for (int ks = 0; ks < 2; ks++) {
            uint32_t a[4][4];
            uint32_t b[4][2];
#pragma unroll
            for (int m = 0; m < 4; m++) {
                float4 av = *(const float4*)&As[(((warpM * 4 + m) * 2 + ks) * 33 + lane) * 4];
                a[m][0] = __float_as_uint(av.x);
                a[m][1] = __float_as_uint(av.y);
                a[m][2] = __float_as_uint(av.z);
                a[m][3] = __float_as_uint(av.w);
            }
#pragma unroll
            for (int nb = 0; nb < 4; nb++) {
                float2 bv = *(const float2*)&Bs[(((warpN * 4 + nb) * 2 + ks) * 33 + lane) * 2];
                b[nb][0] = __float_as_uint(bv.x);
                b[nb][1] = __float_as_uint(bv.y);
            }
#pragma unroll
            for (int m = 0; m < 4; m++)
#pragma unroll
                for (int nb = 0; nb < 4; nb++)
                    mma_tf32(c[m][nb], a[m], b[nb]);
        }
        __syncthreads();
    }

    const int g  = lane >> 2;
    const int tg = lane & 3;
#pragma unroll
    for (int m = 0; m < 4; m++) {
#pragma unroll
        for (int nb = 0; nb < 4; nb++) {
            int row = row0 + warpM * 64 + m * 16 + g;
            int col = co + warpN * 32 + nb * 8 + tg * 2;
            if (row < n) {
                if constexpr (sizeof(OutT) == 2)
                    *(__half2*)&H[(size_t)row * OUTC + col] =
                        __floats2half2_rn(c[m][nb][0], c[m][nb][1]);
                else
                    *(float2*)&H[(size_t)row * OUTC + col] =
                        make_float2(c[m][nb][0], c[m][nb][1]);
            }
            if (row + 8 < n) {
                if constexpr (sizeof(OutT) == 2)
                    *(__half2*)&H[(size_t)(row + 8) * OUTC + col] =
                        __floats2half2_rn(c[m][nb][2], c[m][nb][3]);
                else
                    *(float2*)&H[(size_t)(row + 8) * OUTC + col] =
                        make_float2(c[m][nb][2], c[m][nb][3]);
            }
        }
    }
}

// ---------------------------------------------------------------------------
// Aggregation from fp16 source: one warp per dst node (16 warps/CTA),
// CSR gather, fp32 accum, 4-way unrolled. OutT = float or __half.
// ---------------------------------------------------------------------------
template <int CH, bool RELU, typename OutT>
__global__ void __launch_bounds__(512) k_agg_h(const __half* __restrict__ H,
                                               OutT* __restrict__ OUT,
                                               const float* __restrict__ bias,
                                               int n) {
    int node = blockIdx.x * 16 + (threadIdx.x >> 5);
    int lane = threadIdx.x & 31;
    if (node >= n) return;

    float di = g_dinv[node];
    int beg = g_off[node];
    int end = g_off[node + 1];

    if (CH == 128) {
        uint2 rw = *(const uint2*)(H + (size_t)node * 128 + lane * 4);
        float2 p0 = __half22float2(*(__half2*)&rw.x);
        float2 p1 = __half22float2(*(__half2*)&rw.y);
        float ns = di * di;
        float4 acc = make_float4(p0.x * ns, p0.y * ns, p1.x * ns, p1.y * ns);
        int j = beg;
        for (; j + 3 < end; j += 4) {
            int   sx[4];
            float nm[4];
            uint2 rv[4];
#pragma unroll
            for (int q = 0; q < 4; q++) sx[q] = g_csr[j + q];
#pragma unroll
            for (int q = 0; q < 4; q++) {
                nm[q] = g_dinv[sx[q]] * di;
                rv[q] = *(const uint2*)(H + (size_t)sx[q] * 128 + lane * 4);
            }
#pragma unroll
            for (int q = 0; q < 4; q++) {
                float2 a0 = __half22float2(*(__half2*)&rv[q].x);
                float2 a1 = __half22float2(*(__half2*)&rv[q].y);
                acc.x += a0.x * nm[q]; acc.y += a0.y * nm[q];
                acc.z += a1.x * nm[q]; acc.w += a1.y * nm[q];
            }
        }
        for (; j < end; j++) {
            int s = g_csr[j];
            float nm = g_dinv[s] * di;
            uint2 r0 = *(const uint2*)(H + (size_t)s * 128 + lane * 4);
            float2 a0 = __half22float2(*(__half2*)&r0.x);
            float2 a1 = __half22float2(*(__half2*)&r0.y);
            acc.x += a0.x * nm; acc.y += a0.y * nm;
            acc.z += a1.x * nm; acc.w += a1.y * nm;
        }
        int cc = lane * 4;
        acc.x += __ldg(&bias[cc]);     acc.y += __ldg(&bias[cc + 1]);
        acc.z += __ldg(&bias[cc + 2]); acc.w += __ldg(&bias[cc + 3]);
        if (RELU) {
            acc.x = fmaxf(acc.x, 0.f); acc.y = fmaxf(acc.y, 0.f);
            acc.z = fmaxf(acc.z, 0.f); acc.w = fmaxf(acc.w, 0.f);
        }
        if constexpr (sizeof(OutT) == 2) {
            uint2 o;
            *(__half2*)&o.x = __floats2half2_rn(acc.x, acc.y);
            *(__half2*)&o.y = __floats2half2_rn(acc.z, acc.w);
            *(uint2*)(OUT + (size_t)node * 128 + lane * 4) = o;
        } else {
            ((float4*)(OUT + (size_t)node * 128))[lane] = acc;
        }
    } else {
        uint32_t rw = *(const uint32_t*)(H + (size_t)node * 64 + lane * 2);
        float2 p = __half22float2(*(__half2*)&rw);
        float ns = di * di;
        float2 acc = make_float2(p.x * ns, p.y * ns);
        int j = beg;
        for (; j + 3 < end; j += 4) {
            int      sx[4];
            float    nm[4];
            uint32_t rv[4];
#pragma unroll
            for (int q = 0; q < 4; q++) sx[q] = g_csr[j + q];
#pragma unroll
            for (int q = 0; q < 4; q++) {
                nm[q] = g_dinv[sx[q]] * di;
                rv[q] = *(const uint32_t*)(H + (size_t)sx[q] * 64 + lane * 2);
            }
#pragma unroll
            for (int q = 0; q < 4; q++) {
                float2 a = __half22float2(*(__half2*)&rv[q]);
                acc.x += a.x * nm[q]; acc.y += a.y * nm[q];
            }
        }
        for (; j < end; j++) {
            int s = g_csr[j];
            float nm = g_dinv[s] * di;
            uint32_t r0 = *(const uint32_t*)(H + (size_t)s * 64 + lane * 2);
            float2 a = __half22float2(*(__half2*)&r0);
            acc.x += a.x * nm; acc.y += a.y * nm;
        }
        int cc = lane * 2;
        acc.x += __ldg(&bias[cc]); acc.y += __ldg(&bias[cc + 1]);
        if (RELU) { acc.x = fmaxf(acc.x, 0.f); acc.y = fmaxf(acc.y, 0.f); }
        if constexpr (sizeof(OutT) == 2) {
            *(__half2*)(OUT + (size_t)node * 64 + lane * 2) =
                __floats2half2_rn(acc.x, acc.y);
        } else {
            ((float2*)(OUT + (size_t)node * 64))[lane] = acc;
        }
    }
}

// ---------------------------------------------------------------------------
extern "C" void kernel_launch(void* const* d_in, const int* in_sizes, int n_in,
                              void* d_out, int out_size) {
    const float* x   = (const float*)d_in[0];
    const int*   ei  = (const int*)d_in[1];   // int32 OR int64 (auto-detected)
    const float* W1  = (const float*)d_in[2];
    const float* b1  = (const float*)d_in[3];
    const float* W2  = (const float*)d_in[4];
    const float* b2  = (const float*)d_in[5];
    float*       out = (float*)d_out;

    const int n = in_sizes[0] / 128;
    const int E = in_sizes[1] / 2;

    __half* d_h;   cudaGetSymbolAddress((void**)&d_h,   g_h);
    __half* d_agg; cudaGetSymbolAddress((void**)&d_agg, g_agg);
    __half* d_t;   cudaGetSymbolAddress((void**)&d_t,   g_t);

    // Side stream for GEMM1 (independent of CSR build) — fork/join via events.
    cudaStream_t s1;
    cudaStreamCreateWithFlags(&s1, cudaStreamNonBlocking);
    cudaEvent_t e_fork, e_join;
    cudaEventCreateWithFlags(&e_fork, cudaEventDisableTiming);
    cudaEventCreateWithFlags(&e_join, cudaEventDisableTiming);

    cudaEventRecord(e_fork, 0);
    cudaStreamWaitEvent(s1, e_fork, 0);
    {
        dim3 grid((n + 255) / 256, 2);
        k_gemm_mma<128, float, __half><<<grid, 256, 0, s1>>>(x, W1, d_h, n);
    }
    cudaEventRecord(e_join, s1);

    // Fused CSR build (count -> scan -> fill in one kernel, grid barriers)
    k_csr<<<CSR_BLOCKS, CSR_THREADS>>>(ei, E, n);

    cudaStreamWaitEvent(0, e_join, 0);

    // aggregate layer 1 (fused self-loop + bias + relu), fp16 -> fp16
    k_agg_h<128, true, __half><<<(n + 15) / 16, 512>>>(d_h, d_agg, b1, n);

    // layer 2: t = relu_h @ W2 (fp16 in, fp16 out)
    {
        dim3 grid((n + 255) / 256, 1);
        k_gemm_mma<64, __half, __half><<<grid, 256>>>(d_agg, W2, d_t, n);
    }

    // aggregate layer 2 directly into d_out (fused bias), fp16 -> fp32
    k_agg_h<64, false, float><<<(n + 15) / 16, 512>>>(d_t, out, b2, n);

    cudaEventDestroy(e_fork);
    cudaEventDestroy(e_join);
    cudaStreamDestroy(s1);
}

// round 16
// speedup vs baseline: 1.2748x; 1.2748x over previous
#include <cuda_runtime.h>
#include <cuda_fp16.h>
#include <stdint.h>

#define N_MAX 50000
#define E_MAX 600000
#define SCAN_BLK 1024
#define NBLK_SCAN ((N_MAX + SCAN_BLK - 1) / SCAN_BLK)   // 49

// Scratch (device globals; no allocation allowed)
__device__ int    g_cnt[N_MAX];          // zero at entry (re-zeroed each run)
__device__ int    g_off[N_MAX + 1];
__device__ int    g_pos[N_MAX];
__device__ int    g_bsum[NBLK_SCAN + 1];
__device__ int    g_flag[NBLK_SCAN + 1]; // cleared by k_count_f each run
__device__ float  g_dinv[N_MAX];
__device__ int    g_csr[E_MAX];
__device__ __half g_h[(size_t)N_MAX * 128];   // x @ W1 (fp16)
__device__ __half g_agg[(size_t)N_MAX * 128]; // aggregated layer-1 (fp16)
__device__ __half g_t[(size_t)N_MAX * 64];    // relu_h @ W2 (fp16)

__device__ __forceinline__ float tf32r(float x) {
    uint32_t u;
    asm("cvt.rna.tf32.f32 %0, %1;" : "=r"(u) : "f"(x));
    return __uint_as_float(u);
}

__device__ __forceinline__ void mma_tf32(float* c, const uint32_t* a, const uint32_t* b) {
    asm volatile(
        "mma.sync.aligned.m16n8k8.row.col.f32.tf32.tf32.f32 "
        "{%0,%1,%2,%3}, {%4,%5,%6,%7}, {%8,%9}, {%0,%1,%2,%3};"
        : "+f"(c[0]), "+f"(c[1]), "+f"(c[2]), "+f"(c[3])
        : "r"(a[0]), "r"(a[1]), "r"(a[2]), "r"(a[3]), "r"(b[0]), "r"(b[1]));
}

// In-block dtype detection: sample 32 odd int32 words.
__device__ __forceinline__ int detect_fmt(const int* __restrict__ raw, int E) {
    int idx = 2 * (threadIdx.x & 31) + 1;
    int hw = (idx < 2 * E) ? raw[idx] : 0;
    unsigned any = __ballot_sync(0xFFFFFFFFu, hw != 0);
    return (any == 0) ? 1 : 0;   // 1 = int64, 0 = int32
}

// ---------------------------------------------------------------------------
// count: 2 edges/thread, fused dtype detect + flag clear
// ---------------------------------------------------------------------------
__global__ void k_count_f(const int* __restrict__ raw, int E, int n) {
    __shared__ int s_fmt;
    if (threadIdx.x < 32) {
        int f = detect_fmt(raw, E);
        if (threadIdx.x == 0) s_fmt = f;
    }
    int gid = blockIdx.x * blockDim.x + threadIdx.x;
    if (gid <= NBLK_SCAN) g_flag[gid] = 0;
    __syncthreads();
    int fmt = s_fmt;

    int base = 2 * gid;
    if (base >= E) return;
    int d0 = fmt ? raw[2 * (E + base)] : raw[E + base];
    int e1 = base + 1;
    int d1 = (e1 < E) ? (fmt ? raw[2 * (E + e1)] : raw[E + e1]) : -1;
    atomicAdd(&g_cnt[min(max(d0, 0), n - 1)], 1);
    if (e1 < E) atomicAdd(&g_cnt[min(max(d1, 0), n - 1)], 1);
}

// ---------------------------------------------------------------------------
// single-kernel scan: per-block 2-level shuffle scan + decoupled lookback
// ---------------------------------------------------------------------------
__global__ void __launch_bounds__(SCAN_BLK) k_scan(int n, int E) {
    __shared__ int warpsum[32];
    __shared__ int pred[2];
    const int b = blockIdx.x;
    const int t = threadIdx.x;
    const int i = b * SCAN_BLK + t;
    const int v = (i < n) ? g_cnt[i] : 0;
    const int lane = t & 31, w = t >> 5;

    int x = v;
#pragma unroll
    for (int d = 1; d < 32; d <<= 1) {
        int y = __shfl_up_sync(0xFFFFFFFFu, x, d);
        if (lane >= d) x += y;
    }
    if (lane == 31) warpsum[w] = x;
    __syncthreads();
    if (w == 0) {
        int s = warpsum[lane];
#pragma unroll
        for (int d = 1; d < 32; d <<= 1) {
            int y = __shfl_up_sync(0xFFFFFFFFu, s, d);
            if (lane >= d) s += y;
        }
        warpsum[lane] = s;
    }
    __syncthreads();
    const int base  = (w > 0) ? warpsum[w - 1] : 0;
    const int total = warpsum[31];

    if (t == 0) {
        g_bsum[b] = total;
        __threadfence();
        ((volatile int*)g_flag)[b] = 1;
    }

    int pv = 0;
    if (t < b) {
        while (((volatile int*)g_flag)[t] == 0) {}
        __threadfence();
        pv = g_bsum[t];
    }
    if (t < 64) {
        int s = pv;
#pragma unroll
        for (int d = 16; d > 0; d >>= 1) s += __shfl_down_sync(0xFFFFFFFFu, s, d);
        if (lane == 0) pred[w] = s;
    }
    __syncthreads();
    const int prefix = pred[0] + pred[1];

    if (i < n) {
        int o = prefix + base + x - v;
        g_off[i] = o;
        g_pos[i] = o;
        g_dinv[i] = rsqrtf((float)v + 1.0f);     // +1 self loop
        g_cnt[i] = 0;                            // re-zero for next replay
    }
    if (b == 0 && t == 0) g_off[n] = E;
}

// ---------------------------------------------------------------------------
// fill: 2 edges/thread, fused dtype detect
// ---------------------------------------------------------------------------
__global__ void k_fill_f(const int* __restrict__ raw, int E, int n) {
    __shared__ int s_fmt;
    if (threadIdx.x < 32) {
        int f = detect_fmt(raw, E);
        if (threadIdx.x == 0) s_fmt = f;
    }
    __syncthreads();
    int fmt = s_fmt;

    int base = 2 * (blockIdx.x * blockDim.x + threadIdx.x);
    if (base >= E) return;
    int s0 = fmt ? raw[2 * base] : raw[base];
    int d0 = fmt ? raw[2 * (E + base)] : raw[E + base];
    int e1 = base + 1;
    int s1 = 0, d1 = 0;
    if (e1 < E) {
        s1 = fmt ? raw[2 * e1] : raw[e1];
        d1 = fmt ? raw[2 * (E + e1)] : raw[E + e1];
    }
    int p0 = atomicAdd(&g_pos[min(max(d0, 0), n - 1)], 1);
    g_csr[p0] = min(max(s0, 0), n - 1);
    if (e1 < E) {
        int p1 = atomicAdd(&g_pos[min(max(d1, 0), n - 1)], 1);
        g_csr[p1] = min(max(s1, 0), n - 1);
    }
}

// ---------------------------------------------------------------------------
// tf32 tensor-core GEMM: H[n, OUTC] = X[n,128] @ W[128, OUTC]
// CTA tile MT x 64, 8 warps (4M x 2N), warp tile (MT/4) x 32, K sliced by 16.
// MFRAG = MT/64 m16-fragments per warp.
// ---------------------------------------------------------------------------
template <int OUTC, int MT, typename InT, typename OutT>
__global__ void __launch_bounds__(256) k_gemm_mma(const InT* __restrict__ X,
                                                  const float* __restrict__ W,
                                                  OutT* __restrict__ H, int n) {
    constexpr int MFRAG = MT / 64;
    __shared__ float As[(MT / 16) * 2 * 33 * 4];
    __shared__ float Bs[16 * 33 * 2];
    const int tid   = threadIdx.x;
    const int lane  = tid & 31;
    const int warp  = tid >> 5;
    const int warpM = warp & 3;
    const int warpN = warp >> 2;
    const int row0  = blockIdx.x * MT;
    const int co    = blockIdx.y * 64;

    float c[MFRAG][4][4];
#pragma unroll
    for (int i = 0; i < MFRAG; i++)
#pragma unroll
        for (int j = 0; j < 4; j++)
#pragma unroll
            for (int r = 0; r < 4; r++) c[i][j][r] = 0.f;

    for (int k0 = 0; k0 < 128; k0 += 16) {
#pragma unroll
        for (int f = tid; f < MT * 4; f += 256) {
            int r  = f >> 2;
            int kq = f & 3;
            int gr = min(row0 + r, n - 1);
            float4 v;
            if constexpr (sizeof(InT) == 2) {
                uint2 hv = *(const uint2*)&X[(size_t)gr * 128 + k0 + kq * 4];
                float2 f0 = __half22float2(*(__half2*)&hv.x);
                float2 f1 = __half22float2(*(__half2*)&hv.y);
                v = make_float4(f0.x, f0.y, f1.x, f1.y);
            } else {
                v = *(const float4*)&X[(size_t)gr * 128 + k0 + kq * 4];
            }
            int grp  = (r >> 4) * 2 + (kq >> 1);
            int lb   = (r & 7) * 4;
            int reg  = (kq & 1) * 2 + ((r >> 3) & 1);
            int sbase = grp * 33 * 4;
            As[(sbase + (lb + 0) * 4) + reg] = tf32r(v.x);
            As[(sbase + (lb + 1) * 4) + reg] = tf32r(v.y);
            As[(sbase + (lb + 2) * 4) + reg] = tf32r(v.z);
            As[(sbase + (lb + 3) * 4) + reg] = tf32r(v.w);
        }
        {
            int k  = tid >> 4;
            int nq = tid & 15;
            float4 v = *(const float4*)&W[(size_t)(k0 + k) * OUTC + co + nq * 4];
            int kstep = k >> 3, tg = k & 3, regb = (k >> 2) & 1;
            float vv[4] = {v.x, v.y, v.z, v.w};
#pragma unroll
            for (int j = 0; j < 4; j++) {
                int nn = nq * 4 + j;
                int grp = (nn >> 3) * 2 + kstep;
                Bs[(grp * 33 + (nn & 7) * 4 + tg) * 2 + regb] = tf32r(vv[j]);
            }
        }
        __syncthreads();

#pragma unroll
        for (int ks = 0; ks < 2; ks++) {
            uint32_t a[MFRAG][4];
            uint32_t b[4][2];
#pragma unroll
            for (int m = 0; m < MFRAG; m++) {
                float4 av = *(const float4*)&As[(((warpM * MFRAG + m) * 2 + ks) * 33 + lane) * 4];
                a[m][0] = __float_as_uint(av.x);
                a[m][1] = __float_as_uint(av.y);
                a[m][2] = __float_as_uint(av.z);
                a[m][3] = __float_as_uint(av.w);
            }
#pragma unroll
            for (int nb = 0; nb < 4; nb++) {
                float2 bv = *(const float2*)&Bs[(((warpN * 4 + nb) * 2 + ks) * 33 + lane) * 2];
                b[nb][0] = __float_as_uint(bv.x);
                b[nb][1] = __float_as_uint(bv.y);
            }
#pragma unroll
            for (int m = 0; m < MFRAG; m++)
#pragma unroll
                for (int nb = 0; nb < 4; nb++)
                    mma_tf32(c[m][nb], a[m], b[nb]);
        }
        __syncthreads();
    }

    const int g  = lane >> 2;
    const int tg = lane & 3;
#pragma unroll
    for (int m = 0; m < MFRAG; m++) {
#pragma unroll
        for (int nb = 0; nb < 4; nb++) {
            int row = row0 + warpM * (MT / 4) + m * 16 + g;
            int col = co + warpN * 32 + nb * 8 + tg * 2;
            if (row < n) {
                if constexpr (sizeof(OutT) == 2)
                    *(__half2*)&H[(size_t)row * OUTC + col] =
                        __floats2half2_rn(c[m][nb][0], c[m][nb][1]);
                else
                    *(float2*)&H[(size_t)row * OUTC + col] =
                        make_float2(c[m][nb][0], c[m][nb][1]);
            }
            if (row + 8 < n) {
                if constexpr (sizeof(OutT) == 2)
                    *(__half2*)&H[(size_t)(row + 8) * OUTC + col] =
                        __floats2half2_rn(c[m][nb][2], c[m][nb][3]);
                else
                    *(float2*)&H[(size_t)(row + 8) * OUTC + col] =
                        make_float2(c[m][nb][2], c[m][nb][3]);
            }
        }
    }
}

// ---------------------------------------------------------------------------
// Aggregation from fp16 source: one warp per dst node, CSR gather, fp32 accum,
// 4-way unrolled. OutT = float or __half.
// ---------------------------------------------------------------------------
template <int CH, bool RELU, typename OutT>
__global__ void __launch_bounds__(256) k_agg_h(const __half* __restrict__ H,
                                               OutT* __restrict__ OUT,
                                               const float* __restrict__ bias,
                                               int n) {
    int node = blockIdx.x * 8 + (threadIdx.x >> 5);
    int lane = threadIdx.x & 31;
    if (node >= n) return;

    float di = g_dinv[node];
    int beg = g_off[node];
    int end = g_off[node + 1];

    if (CH == 128) {
        uint2 rw = *(const uint2*)(H + (size_t)node * 128 + lane * 4);
        float2 p0 = __half22float2(*(__half2*)&rw.x);
        float2 p1 = __half22float2(*(__half2*)&rw.y);
        float ns = di * di;
        float4 acc = make_float4(p0.x * ns, p0.y * ns, p1.x * ns, p1.y * ns);
        int j = beg;
        for (; j + 3 < end; j += 4) {
            int   sx[4];
            float nm[4];
            uint2 rv[4];
#pragma unroll
            for (int q = 0; q < 4; q++) sx[q] = g_csr[j + q];
#pragma unroll
            for (int q = 0; q < 4; q++) {
                nm[q] = g_dinv[sx[q]] * di;
                rv[q] = *(const uint2*)(H + (size_t)sx[q] * 128 + lane * 4);
            }
#pragma unroll
            for (int q = 0; q < 4; q++) {
                float2 a0 = __half22float2(*(__half2*)&rv[q].x);
                float2 a1 = __half22float2(*(__half2*)&rv[q].y);
                acc.x += a0.x * nm[q]; acc.y += a0.y * nm[q];
                acc.z += a1.x * nm[q]; acc.w += a1.y * nm[q];
            }
        }
        for (; j < end; j++) {
            int s = g_csr[j];
            float nm = g_dinv[s] * di;
            uint2 r0 = *(const uint2*)(H + (size_t)s * 128 + lane * 4);
            float2 a0 = __half22float2(*(__half2*)&r0.x);
            float2 a1 = __half22float2(*(__half2*)&r0.y);
            acc.x += a0.x * nm; acc.y += a0.y * nm;
            acc.z += a1.x * nm; acc.w += a1.y * nm;
        }
        int cc = lane * 4;
        acc.x += __ldg(&bias[cc]);     acc.y += __ldg(&bias[cc + 1]);
        acc.z += __ldg(&bias[cc + 2]); acc.w += __ldg(&bias[cc + 3]);
        if (RELU) {
            acc.x = fmaxf(acc.x, 0.f); acc.y = fmaxf(acc.y, 0.f);
            acc.z = fmaxf(acc.z, 0.f); acc.w = fmaxf(acc.w, 0.f);
        }
        if constexpr (sizeof(OutT) == 2) {
            uint2 o;
            *(__half2*)&o.x = __floats2half2_rn(acc.x, acc.y);
            *(__half2*)&o.y = __floats2half2_rn(acc.z, acc.w);
            *(uint2*)(OUT + (size_t)node * 128 + lane * 4) = o;
        } else {
            ((float4*)(OUT + (size_t)node * 128))[lane] = acc;
        }
    } else {
        uint32_t rw = *(const uint32_t*)(H + (size_t)node * 64 + lane * 2);
        float2 p = __half22float2(*(__half2*)&rw);
        float ns = di * di;
        float2 acc = make_float2(p.x * ns, p.y * ns);
        int j = beg;
        for (; j + 3 < end; j += 4) {
            int      sx[4];
            float    nm[4];
            uint32_t rv[4];
#pragma unroll
            for (int q = 0; q < 4; q++) sx[q] = g_csr[j + q];
#pragma unroll
            for (int q = 0; q < 4; q++) {
                nm[q] = g_dinv[sx[q]] * di;
                rv[q] = *(const uint32_t*)(H + (size_t)sx[q] * 64 + lane * 2);
            }
#pragma unroll
            for (int q = 0; q < 4; q++) {
                float2 a = __half22float2(*(__half2*)&rv[q]);
                acc.x += a.x * nm[q]; acc.y += a.y * nm[q];
            }
        }
        for (; j < end; j++) {
            int s = g_csr[j];
            float nm = g_dinv[s] * di;
            uint32_t r0 = *(const uint32_t*)(H + (size_t)s * 64 + lane * 2);
            float2 a = __half22float2(*(__half2*)&r0);
            acc.x += a.x * nm; acc.y += a.y * nm;
        }
        int cc = lane * 2;
        acc.x += __ldg(&bias[cc]); acc.y += __ldg(&bias[cc + 1]);
        if (RELU) { acc.x = fmaxf(acc.x, 0.f); acc.y = fmaxf(acc.y, 0.f); }
        if constexpr (sizeof(OutT) == 2) {
            *(__half2*)(OUT + (size_t)node * 64 + lane * 2) =
                __floats2half2_rn(acc.x, acc.y);
        } else {
            ((float2*)(OUT + (size_t)node * 64))[lane] = acc;
        }
    }
}

// ---------------------------------------------------------------------------
extern "C" void kernel_launch(void* const* d_in, const int* in_sizes, int n_in,
                              void* d_out, int out_size) {
    const float* x   = (const float*)d_in[0];
    const int*   ei  = (const int*)d_in[1];   // int32 OR int64 (auto-detected)
    const float* W1  = (const float*)d_in[2];
    const float* b1  = (const float*)d_in[3];
    const float* W2  = (const float*)d_in[4];
    const float* b2  = (const float*)d_in[5];
    float*       out = (float*)d_out;

    const int n = in_sizes[0] / 128;
    const int E = in_sizes[1] / 2;

    __half* d_h;   cudaGetSymbolAddress((void**)&d_h,   g_h);
    __half* d_agg; cudaGetSymbolAddress((void**)&d_agg, g_agg);
    __half* d_t;   cudaGetSymbolAddress((void**)&d_t,   g_t);

    const int T = 256;
    const int halfE = (E + 1) / 2;

    // Side stream for GEMM1 (independent of CSR build) — fork/join via events.
    cudaStream_t s1;
    cudaStreamCreateWithFlags(&s1, cudaStreamNonBlocking);
    cudaEvent_t e_fork, e_join;
    cudaEventCreateWithFlags(&e_fork, cudaEventDisableTiming);
    cudaEventCreateWithFlags(&e_join, cudaEventDisableTiming);

    cudaEventRecord(e_fork, 0);
    cudaStreamWaitEvent(s1, e_fork, 0);
    {
        dim3 grid((n + 255) / 256, 2);
        k_gemm_mma<128, 256, float, __half><<<grid, 256, 0, s1>>>(x, W1, d_h, n);
    }
    cudaEventRecord(e_join, s1);

    // CSR build + dinv on the main stream, concurrent with GEMM1 (3 kernels)
    k_count_f<<<(halfE + T - 1) / T, T>>>(ei, E, n);
    k_scan<<<NBLK_SCAN, SCAN_BLK>>>(n, E);
    k_fill_f<<<(halfE + T - 1) / T, T>>>(ei, E, n);

    cudaStreamWaitEvent(0, e_join, 0);

    // aggregate layer 1 (fused self-loop + bias + relu), fp16 -> fp16
    k_agg_h<128, true, __half><<<(n + 7) / 8, 256>>>(d_h, d_agg, b1, n);

    // layer 2: t = relu_h @ W2 (fp16 in, fp16 out), 128-row tiles
    {
        dim3 grid((n + 127) / 128, 1);
        k_gemm_mma<64, 128, __half, __half><<<grid, 256>>>(d_agg, W2, d_t, n);
    }

    // aggregate layer 2 directly into d_out (fused bias), fp16 -> fp32
    k_agg_h<64, false, float><<<(n + 7) / 8, 256>>>(d_t, out, b2, n);

    cudaEventDestroy(e_fork);
    cudaEventDestroy(e_join);
    cudaStreamDestroy(s1);
}